// round 9
// baseline (speedup 1.0000x reference)
#include <cuda_runtime.h>
#include <cuda_bf16.h>
#include <cstddef>

#define S_LEN 2048
#define B_DIM 64
#define I_DIM 512
#define H_DIM 512
#define BH (B_DIM * H_DIM)          // 32768
#define GX_COLS 1024                // z gates [0,512), n gates [512,1024)

// Scratch: gx[t][b][g], g in 0..1023 maps to weight rows 512+g. 512 MB.
__device__ float g_gx[(size_t)S_LEN * B_DIM * GX_COLS];
// Sense-reversing group barrier state (8 groups) — used only by the fallback
// kernel. Returns to {0,0} after the even number (2048) of flips per launch.
__device__ int g_cnt[8];
__device__ int g_sense[8];

typedef unsigned long long ull;

__device__ __forceinline__ ull fma2(ull a, ull b, ull c) {
    ull d;
    asm("fma.rn.f32x2 %0, %1, %2, %3;" : "=l"(d) : "l"(a), "l"(b), "l"(c));
    return d;
}
__device__ __forceinline__ float sum2(ull u) {
    float lo, hi;
    asm("mov.b64 {%0,%1}, %2;" : "=f"(lo), "=f"(hi) : "l"(u));
    return lo + hi;
}
__device__ __forceinline__ void st_rel(int* p, int v) {
    asm volatile("st.release.gpu.global.b32 [%0], %1;" :: "l"(p), "r"(v) : "memory");
}
__device__ __forceinline__ int ld_acq(const int* p) {
    int v;
    asm volatile("ld.acquire.gpu.global.b32 %0, [%1];" : "=r"(v) : "l"(p) : "memory");
    return v;
}
// Fast gates: MUFU-based, ~1e-7 abs error, saturate correctly at +-inf.
__device__ __forceinline__ float fsig(float x) {
    return __fdividef(1.0f, 1.0f + __expf(-x));
}
__device__ __forceinline__ float ftanh(float x) {
    return 1.0f - __fdividef(2.0f, __expf(2.0f * x) + 1.0f);
}

// ---------------------------------------------------------------------------
// Kernel 1: gx = x @ Wih[512:1536]^T + (bias_ih + bias_hh)[512:1536]
// M=131072, N=1024, K=512. BM=BN=128, BK=16, 256 threads, 8x8 f32x2 tile.
// (unchanged — proven R2..R7)
// ---------------------------------------------------------------------------
__global__ void __launch_bounds__(256, 1)
gx_gemm(const float* __restrict__ x, const float* __restrict__ wih,
        const float* __restrict__ bih, const float* __restrict__ bhh) {
    __shared__ ull As2[8 * 130];
    __shared__ ull Bs2[8 * 130];

    const int tid = threadIdx.x;
    const int tx = tid & 15;
    const int ty = tid >> 4;
    const int n0 = blockIdx.x * 128;
    const size_t m0 = (size_t)blockIdx.y * 128;
    const int r = tid >> 1;
    const int half = tid & 1;
    const int kp0 = half * 4;

    float bz[8];
#pragma unroll
    for (int j = 0; j < 8; j++) {
        int n = n0 + tx + 16 * j;
        bz[j] = bih[512 + n] + bhh[512 + n];
    }

    ull acc[8][8];
#pragma unroll
    for (int i = 0; i < 8; i++)
#pragma unroll
        for (int j = 0; j < 8; j++) acc[i][j] = 0ull;

    const float* arow = x + (m0 + r) * 512 + half * 8;
    const float* brow = wih + (size_t)(512 + n0 + r) * 512 + half * 8;

    ulonglong2 A0 = *(const ulonglong2*)(arow);
    ulonglong2 A1 = *(const ulonglong2*)(arow + 4);
    ulonglong2 B0 = *(const ulonglong2*)(brow);
    ulonglong2 B1 = *(const ulonglong2*)(brow + 4);

    for (int kt = 0; kt < 32; kt++) {
        As2[(kp0 + 0) * 130 + r] = A0.x;
        As2[(kp0 + 1) * 130 + r] = A0.y;
        As2[(kp0 + 2) * 130 + r] = A1.x;
        As2[(kp0 + 3) * 130 + r] = A1.y;
        Bs2[(kp0 + 0) * 130 + r] = B0.x;
        Bs2[(kp0 + 1) * 130 + r] = B0.y;
        Bs2[(kp0 + 2) * 130 + r] = B1.x;
        Bs2[(kp0 + 3) * 130 + r] = B1.y;
        __syncthreads();
        if (kt < 31) {
            int ko = (kt + 1) * 16;
            A0 = *(const ulonglong2*)(arow + ko);
            A1 = *(const ulonglong2*)(arow + ko + 4);
            B0 = *(const ulonglong2*)(brow + ko);
            B1 = *(const ulonglong2*)(brow + ko + 4);
        }
#pragma unroll
        for (int kp = 0; kp < 8; kp++) {
            ull av[8], bv[8];
            const ulonglong2* ap = (const ulonglong2*)&As2[kp * 130 + ty * 8];
#pragma unroll
            for (int i2 = 0; i2 < 4; i2++) {
                ulonglong2 t2 = ap[i2];
                av[i2 * 2] = t2.x;
                av[i2 * 2 + 1] = t2.y;
            }
#pragma unroll
            for (int j = 0; j < 8; j++) bv[j] = Bs2[kp * 130 + tx + 16 * j];
#pragma unroll
            for (int i = 0; i < 8; i++)
#pragma unroll
                for (int j = 0; j < 8; j++) acc[i][j] = fma2(av[i], bv[j], acc[i][j]);
        }
        __syncthreads();
    }

#pragma unroll
    for (int i = 0; i < 8; i++) {
        float* orow = g_gx + (m0 + ty * 8 + i) * (size_t)GX_COLS + n0 + tx;
#pragma unroll
        for (int j = 0; j < 8; j++) orow[16 * j] = sum2(acc[i][j]) + bz[j];
    }
}

// ---------------------------------------------------------------------------
// Recurrence body shared by both sync variants (R7 compute mapping, proven).
// SYNC_MODE 0 = atomic sense barrier (fallback), 1 = 16-CTA cluster barrier.
// ---------------------------------------------------------------------------
template <int SYNC_MODE>
__device__ __forceinline__ void rec_body(const float* __restrict__ h0,
                                         const float* __restrict__ whh,
                                         float* __restrict__ out) {
    __shared__ float4 h_s4[8][8][17];   // [b][q][kp] swizzled, k=(kp*8+q)*4+e

    const int tid = threadIdx.x;
    const int bx = blockIdx.x;
    const int grp = bx >> 4;
    const int gb = grp * 8;
    const int hd0 = (bx & 15) * 32;
    const int lane = tid & 31;
    const int wid = tid >> 5;
    const int kp = lane & 15;
    const int h1 = lane >> 4;
    const int hdg = wid * 2 + h1;
    const int hdp = hd0 + hdg * 2;      // this thread's hd pair base
    const bool ep = (kp < 8);           // epilogue lane: handles batch eb
    const int eb = kp;
    const int k4h = hdp >> 2;           // h_old float4 slot for this hd pair

    // Step-invariant weights in registers (128 floats).
    ulonglong2 wz0[8], wz1[8], wn0[8], wn1[8];
    {
        const ulonglong2* pz0 = (const ulonglong2*)(whh + (size_t)(512 + hdp) * 512 + kp * 32);
        const ulonglong2* pz1 = (const ulonglong2*)(whh + (size_t)(513 + hdp) * 512 + kp * 32);
        const ulonglong2* pn0 = (const ulonglong2*)(whh + (size_t)(1024 + hdp) * 512 + kp * 32);
        const ulonglong2* pn1 = (const ulonglong2*)(whh + (size_t)(1025 + hdp) * 512 + kp * 32);
#pragma unroll
        for (int q = 0; q < 8; q++) {
            wz0[q] = pz0[q];
            wz1[q] = pz1[q];
            wn0[q] = pn0[q];
            wn1[q] = pn1[q];
        }
    }

    // Stage h(-1) = h_0 into swizzled SMEM.
    {
        int b = tid >> 5, rr = tid & 31;
        const float4* src = (const float4*)(h0 + (size_t)(gb + b) * 512);
#pragma unroll
        for (int j = 0; j < 4; j++) {
            int k4 = j * 32 + rr;
            h_s4[b][k4 & 7][k4 >> 3] = __ldcg(src + k4);
        }
    }
    __syncthreads();

    int sense = 0;

    for (int t = 0; t < S_LEN; t++) {
        // Distributed prefetch: each epilogue lane loads only its own cells.
        float2 pgz = make_float2(0.f, 0.f), pgn = make_float2(0.f, 0.f);
        if (ep) {
            const float* gxt = g_gx + (size_t)t * B_DIM * GX_COLS + (size_t)(gb + eb) * GX_COLS;
            pgz = __ldcg((const float2*)(gxt + hdp));
            pgn = __ldcg((const float2*)(gxt + 512 + hdp));
        }

        float mz0 = 0.f, mz1 = 0.f, mn0 = 0.f, mn1 = 0.f;
#pragma unroll
        for (int b = 0; b < 8; b++) {
            ull az0 = 0, az1 = 0, an0 = 0, an1 = 0;
#pragma unroll
            for (int q = 0; q < 8; q++) {
                ulonglong2 h2 = *(const ulonglong2*)&h_s4[b][q][kp];
                az0 = fma2(wz0[q].x, h2.x, az0);
                az0 = fma2(wz0[q].y, h2.y, az0);
                az1 = fma2(wz1[q].x, h2.x, az1);
                az1 = fma2(wz1[q].y, h2.y, az1);
                an0 = fma2(wn0[q].x, h2.x, an0);
                an0 = fma2(wn0[q].y, h2.y, an0);
                an1 = fma2(wn1[q].x, h2.x, an1);
                an1 = fma2(wn1[q].y, h2.y, an1);
            }
            float rz0 = sum2(az0), rz1 = sum2(az1);
            float rn0 = sum2(an0), rn1 = sum2(an1);
#pragma unroll
            for (int off = 1; off < 16; off <<= 1) {
                rz0 += __shfl_xor_sync(0xffffffffu, rz0, off);
                rz1 += __shfl_xor_sync(0xffffffffu, rz1, off);
                rn0 += __shfl_xor_sync(0xffffffffu, rn0, off);
                rn1 += __shfl_xor_sync(0xffffffffu, rn1, off);
            }
            // All 16 lanes of this half now hold identical sums; lane kp==b
            // keeps batch b's values for the distributed epilogue.
            if (kp == b) { mz0 = rz0; mz1 = rz1; mn0 = rn0; mn1 = rn1; }
        }

        // Distributed epilogue: lanes kp<8 each update (batch eb, hd pair).
        if (ep) {
            float4 ho4 = h_s4[eb][k4h & 7][k4h >> 3];
            float ho0 = (hdp & 2) ? ho4.z : ho4.x;
            float ho1 = (hdp & 2) ? ho4.w : ho4.y;
            float z0 = fsig(pgz.x + mz0);
            float z1 = fsig(pgz.y + mz1);
            float n0v = ftanh(pgn.x + mn0);
            float n1v = ftanh(pgn.y + mn1);
            float2 hv;
            hv.x = ho0 + z0 * (n0v - ho0);
            hv.y = ho1 + z1 * (n1v - ho1);
            float* dst = out + (size_t)t * BH + (size_t)(gb + eb) * 512 + hdp;
            *(float2*)dst = hv;
            if (t == S_LEN - 1) {
                float* dn = out + (size_t)S_LEN * BH + (size_t)(gb + eb) * 512 + hdp;
                *(float2*)dn = hv;
            }
        }

        if (SYNC_MODE == 1) {
            // Cluster barrier: arrive (release, cluster scope) orders this
            // thread's global h stores for all in-cluster readers; wait
            // (acquire) makes peers' stores visible. All threads arrive
            // only after their own h_s4 reads, so the restage below cannot
            // race the compute reads either.
            asm volatile("barrier.cluster.arrive.aligned;" ::: "memory");
            asm volatile("barrier.cluster.wait.aligned;" ::: "memory");
        } else {
            __syncthreads();
            sense ^= 1;
            if (tid == 0) {
                asm volatile("fence.acq_rel.gpu;" ::: "memory");
                if (atomicAdd(&g_cnt[grp], 1) == 15) {
                    g_cnt[grp] = 0;
                    st_rel(&g_sense[grp], sense);
                } else {
                    while (ld_acq(&g_sense[grp]) != sense) __nanosleep(32);
                }
            }
            __syncthreads();
        }

        // Restage h[t] from out (L2) into swizzled SMEM.
        {
            int b = tid >> 5, rr = tid & 31;
            const float4* src = (const float4*)(out + (size_t)t * BH + (size_t)(gb + b) * 512);
#pragma unroll
            for (int j = 0; j < 4; j++) {
                int k4 = j * 32 + rr;
                h_s4[b][k4 & 7][k4 >> 3] = __ldcg(src + k4);
            }
        }
        __syncthreads();
    }
}

__global__ void __launch_bounds__(256, 1)
rec_kernel(const float* __restrict__ h0, const float* __restrict__ whh,
           float* __restrict__ out) {
    rec_body<0>(h0, whh, out);
}

__global__ void __launch_bounds__(256, 1)
rec_kernel_cluster(const float* __restrict__ h0, const float* __restrict__ whh,
                   float* __restrict__ out) {
    rec_body<1>(h0, whh, out);
}

extern "C" void kernel_launch(void* const* d_in, const int* in_sizes, int n_in,
                              void* d_out, int out_size) {
    const float* x   = (const float*)d_in[0];  // (S, B, I)
    const float* h0  = (const float*)d_in[1];  // (1, B, H)
    const float* wih = (const float*)d_in[2];  // (3H, I)
    const float* whh = (const float*)d_in[3];  // (3H, H)
    const float* bih = (const float*)d_in[4];  // (3H,)
    const float* bhh = (const float*)d_in[5];  // (3H,)
    float* out = (float*)d_out;                // (1,S,B,H) then (1,B,H)

    dim3 ggrid(8, 1024);
    gx_gemm<<<ggrid, 256>>>(x, wih, bih, bhh);

    // Prefer the 16-CTA-cluster recurrence; validate support host-side
    // (deterministic per device) and fall back to the atomic-barrier kernel.
    bool use_cluster = false;
    cudaLaunchConfig_t cfg = {};
    cfg.gridDim = dim3(128, 1, 1);
    cfg.blockDim = dim3(256, 1, 1);
    cfg.dynamicSmemBytes = 0;
    cfg.stream = 0;
    cudaLaunchAttribute attrs[1];
    attrs[0].id = cudaLaunchAttributeClusterDimension;
    attrs[0].val.clusterDim.x = 16;
    attrs[0].val.clusterDim.y = 1;
    attrs[0].val.clusterDim.z = 1;
    cfg.attrs = attrs;
    cfg.numAttrs = 1;

    if (cudaFuncSetAttribute((const void*)rec_kernel_cluster,
                             cudaFuncAttributeNonPortableClusterSizeAllowed,
                             1) == cudaSuccess) {
        int nclusters = 0;
        if (cudaOccupancyMaxActiveClusters(&nclusters, (const void*)rec_kernel_cluster,
                                           &cfg) == cudaSuccess &&
            nclusters >= 8) {
            use_cluster = true;
        }
    }
    cudaGetLastError();  // clear any sticky probe error before capture launches

    if (use_cluster) {
        cudaLaunchKernelEx(&cfg, rec_kernel_cluster, h0, whh, out);
    } else {
        rec_kernel<<<128, 256>>>(h0, whh, out);
    }
}

// round 10
// speedup vs baseline: 1.3324x; 1.3324x over previous
#include <cuda_runtime.h>
#include <cuda_bf16.h>
#include <cstddef>

#define S_LEN 2048
#define B_DIM 64
#define I_DIM 512
#define H_DIM 512
#define BH (B_DIM * H_DIM)          // 32768
#define GX_COLS 1024                // z gates [0,512), n gates [512,1024)

// Scratch: gx[t][b][g], g in 0..1023 maps to weight rows 512+g. 512 MB.
__device__ float g_gx[(size_t)S_LEN * B_DIM * GX_COLS];
// Per-CTA monotone step flags for batch halves A (b 0..3) and B (b 4..7).
// Each CTA increments its own flag exactly S_LEN times per launch, so all
// flags stay equal across launches; fbase (read at entry) makes comparisons
// replay-safe.
__device__ int g_fA[128];
__device__ int g_fB[128];

typedef unsigned long long ull;

__device__ __forceinline__ ull fma2(ull a, ull b, ull c) {
    ull d;
    asm("fma.rn.f32x2 %0, %1, %2, %3;" : "=l"(d) : "l"(a), "l"(b), "l"(c));
    return d;
}
__device__ __forceinline__ float sum2(ull u) {
    float lo, hi;
    asm("mov.b64 {%0,%1}, %2;" : "=f"(lo), "=f"(hi) : "l"(u));
    return lo + hi;
}
__device__ __forceinline__ void st_rel(int* p, int v) {
    asm volatile("st.release.gpu.global.b32 [%0], %1;" :: "l"(p), "r"(v) : "memory");
}
__device__ __forceinline__ int ld_acq(const int* p) {
    int v;
    asm volatile("ld.acquire.gpu.global.b32 %0, [%1];" : "=r"(v) : "l"(p) : "memory");
    return v;
}
// Fast gates: MUFU-based, ~1e-7 abs error, saturate correctly at +-inf.
__device__ __forceinline__ float fsig(float x) {
    return __fdividef(1.0f, 1.0f + __expf(-x));
}
__device__ __forceinline__ float ftanh(float x) {
    return 1.0f - __fdividef(2.0f, __expf(2.0f * x) + 1.0f);
}

// ---------------------------------------------------------------------------
// Kernel 1: gx = x @ Wih[512:1536]^T + (bias_ih + bias_hh)[512:1536]
// M=131072, N=1024, K=512. BM=BN=128, BK=16, 256 threads, 8x8 f32x2 tile.
// (unchanged — proven R2..R8)
// ---------------------------------------------------------------------------
__global__ void __launch_bounds__(256, 1)
gx_gemm(const float* __restrict__ x, const float* __restrict__ wih,
        const float* __restrict__ bih, const float* __restrict__ bhh) {
    __shared__ ull As2[8 * 130];
    __shared__ ull Bs2[8 * 130];

    const int tid = threadIdx.x;
    const int tx = tid & 15;
    const int ty = tid >> 4;
    const int n0 = blockIdx.x * 128;
    const size_t m0 = (size_t)blockIdx.y * 128;
    const int r = tid >> 1;
    const int half = tid & 1;
    const int kp0 = half * 4;

    float bz[8];
#pragma unroll
    for (int j = 0; j < 8; j++) {
        int n = n0 + tx + 16 * j;
        bz[j] = bih[512 + n] + bhh[512 + n];
    }

    ull acc[8][8];
#pragma unroll
    for (int i = 0; i < 8; i++)
#pragma unroll
        for (int j = 0; j < 8; j++) acc[i][j] = 0ull;

    const float* arow = x + (m0 + r) * 512 + half * 8;
    const float* brow = wih + (size_t)(512 + n0 + r) * 512 + half * 8;

    ulonglong2 A0 = *(const ulonglong2*)(arow);
    ulonglong2 A1 = *(const ulonglong2*)(arow + 4);
    ulonglong2 B0 = *(const ulonglong2*)(brow);
    ulonglong2 B1 = *(const ulonglong2*)(brow + 4);

    for (int kt = 0; kt < 32; kt++) {
        As2[(kp0 + 0) * 130 + r] = A0.x;
        As2[(kp0 + 1) * 130 + r] = A0.y;
        As2[(kp0 + 2) * 130 + r] = A1.x;
        As2[(kp0 + 3) * 130 + r] = A1.y;
        Bs2[(kp0 + 0) * 130 + r] = B0.x;
        Bs2[(kp0 + 1) * 130 + r] = B0.y;
        Bs2[(kp0 + 2) * 130 + r] = B1.x;
        Bs2[(kp0 + 3) * 130 + r] = B1.y;
        __syncthreads();
        if (kt < 31) {
            int ko = (kt + 1) * 16;
            A0 = *(const ulonglong2*)(arow + ko);
            A1 = *(const ulonglong2*)(arow + ko + 4);
            B0 = *(const ulonglong2*)(brow + ko);
            B1 = *(const ulonglong2*)(brow + ko + 4);
        }
#pragma unroll
        for (int kp = 0; kp < 8; kp++) {
            ull av[8], bv[8];
            const ulonglong2* ap = (const ulonglong2*)&As2[kp * 130 + ty * 8];
#pragma unroll
            for (int i2 = 0; i2 < 4; i2++) {
                ulonglong2 t2 = ap[i2];
                av[i2 * 2] = t2.x;
                av[i2 * 2 + 1] = t2.y;
            }
#pragma unroll
            for (int j = 0; j < 8; j++) bv[j] = Bs2[kp * 130 + tx + 16 * j];
#pragma unroll
            for (int i = 0; i < 8; i++)
#pragma unroll
                for (int j = 0; j < 8; j++) acc[i][j] = fma2(av[i], bv[j], acc[i][j]);
        }
        __syncthreads();
    }

#pragma unroll
    for (int i = 0; i < 8; i++) {
        float* orow = g_gx + (m0 + ty * 8 + i) * (size_t)GX_COLS + n0 + tx;
#pragma unroll
        for (int j = 0; j < 8; j++) orow[16 * j] = sum2(acc[i][j]) + bz[j];
    }
}

// ---------------------------------------------------------------------------
// Kernel 2: recurrence — R7 compute mapping with SPLIT-WAVE pipelining.
// 128 CTAs = 8 groups x 16 CTAs; group g: batches 8g..8g+7; CTA c: h-dims
// [32c, 32c+32). 256 threads; thread (wid,lane): kp = lane&15 owns k slice
// [32kp, 32kp+32) of rows {z0,z1,n0,n1} of hd pair hd0 + (wid*2+(lane>>4))*2.
// Each step is two batch-halves A (b 0..3) and B (b 4..7) with separate
// flags; each flag's poll executes one compute-half after its release, so
// barrier/exchange latency hides under compute.
// ---------------------------------------------------------------------------
__global__ void __launch_bounds__(256, 1)
rec_kernel(const float* __restrict__ h0, const float* __restrict__ whh,
           float* __restrict__ out) {
    __shared__ float4 h_s4[8][8][17];   // [b][q][kp] swizzled, k=(kp*8+q)*4+e

    const int tid = threadIdx.x;
    const int bx = blockIdx.x;
    const int grp = bx >> 4;
    const int gb = grp * 8;
    const int hd0 = (bx & 15) * 32;
    const int lane = tid & 31;
    const int wid = tid >> 5;
    const int kp = lane & 15;
    const int h1 = lane >> 4;
    const int hdg = wid * 2 + h1;
    const int hdp = hd0 + hdg * 2;      // this thread's hd pair base
    const bool ep = (kp < 8);           // epilogue lane: handles batch eb
    const int eb = kp;
    const int k4h = hdp >> 2;           // h_old float4 slot for this hd pair

    const int fbase = ld_acq(&g_fA[bx]);  // == all group flags at launch

    // Step-invariant weights in registers (128 floats).
    ulonglong2 wz0[8], wz1[8], wn0[8], wn1[8];
    {
        const ulonglong2* pz0 = (const ulonglong2*)(whh + (size_t)(512 + hdp) * 512 + kp * 32);
        const ulonglong2* pz1 = (const ulonglong2*)(whh + (size_t)(513 + hdp) * 512 + kp * 32);
        const ulonglong2* pn0 = (const ulonglong2*)(whh + (size_t)(1024 + hdp) * 512 + kp * 32);
        const ulonglong2* pn1 = (const ulonglong2*)(whh + (size_t)(1025 + hdp) * 512 + kp * 32);
#pragma unroll
        for (int q = 0; q < 8; q++) {
            wz0[q] = pz0[q];
            wz1[q] = pz1[q];
            wn0[q] = pn0[q];
            wn1[q] = pn1[q];
        }
    }

    // Stage h(-1) = h_0 into swizzled SMEM (both halves).
    {
        int b = tid >> 5, rr = tid & 31;
        const float4* src = (const float4*)(h0 + (size_t)(gb + b) * 512);
#pragma unroll
        for (int j = 0; j < 4; j++) {
            int k4 = j * 32 + rr;
            h_s4[b][k4 & 7][k4 >> 3] = __ldcg(src + k4);
        }
    }
    __syncthreads();

    for (int t = 0; t < S_LEN; t++) {
        // Prefetch gx[t] cells for both halves (lanes kp<8; batch eb=kp).
        float2 pgz = make_float2(0.f, 0.f), pgn = make_float2(0.f, 0.f);
        if (ep) {
            const float* gxt = g_gx + (size_t)t * B_DIM * GX_COLS + (size_t)(gb + eb) * GX_COLS;
            pgz = __ldcg((const float2*)(gxt + hdp));
            pgn = __ldcg((const float2*)(gxt + 512 + hdp));
        }

        // ---------------- half A: batches 0..3 (reads h_s4[0..3]) ----------
        {
            float mz0 = 0.f, mz1 = 0.f, mn0 = 0.f, mn1 = 0.f;
#pragma unroll
            for (int b = 0; b < 4; b++) {
                ull az0 = 0, az1 = 0, an0 = 0, an1 = 0;
#pragma unroll
                for (int q = 0; q < 8; q++) {
                    ulonglong2 h2 = *(const ulonglong2*)&h_s4[b][q][kp];
                    az0 = fma2(wz0[q].x, h2.x, az0);
                    az0 = fma2(wz0[q].y, h2.y, az0);
                    az1 = fma2(wz1[q].x, h2.x, az1);
                    az1 = fma2(wz1[q].y, h2.y, az1);
                    an0 = fma2(wn0[q].x, h2.x, an0);
                    an0 = fma2(wn0[q].y, h2.y, an0);
                    an1 = fma2(wn1[q].x, h2.x, an1);
                    an1 = fma2(wn1[q].y, h2.y, an1);
                }
                float rz0 = sum2(az0), rz1 = sum2(az1);
                float rn0 = sum2(an0), rn1 = sum2(an1);
#pragma unroll
                for (int off = 1; off < 16; off <<= 1) {
                    rz0 += __shfl_xor_sync(0xffffffffu, rz0, off);
                    rz1 += __shfl_xor_sync(0xffffffffu, rz1, off);
                    rn0 += __shfl_xor_sync(0xffffffffu, rn0, off);
                    rn1 += __shfl_xor_sync(0xffffffffu, rn1, off);
                }
                if (kp == b) { mz0 = rz0; mz1 = rz1; mn0 = rn0; mn1 = rn1; }
            }
            if (kp < 4) {  // epilogue for batches 0..3 (eb = kp)
                float4 ho4 = h_s4[eb][k4h & 7][k4h >> 3];
                float ho0 = (hdp & 2) ? ho4.z : ho4.x;
                float ho1 = (hdp & 2) ? ho4.w : ho4.y;
                float z0 = fsig(pgz.x + mz0);
                float z1 = fsig(pgz.y + mz1);
                float n0v = ftanh(pgn.x + mn0);
                float n1v = ftanh(pgn.y + mn1);
                float2 hv;
                hv.x = ho0 + z0 * (n0v - ho0);
                hv.y = ho1 + z1 * (n1v - ho1);
                float* dst = out + (size_t)t * BH + (size_t)(gb + eb) * 512 + hdp;
                *(float2*)dst = hv;
                if (t == S_LEN - 1)
                    *(float2*)(out + (size_t)S_LEN * BH + (size_t)(gb + eb) * 512 + hdp) = hv;
            }
        }
        __syncthreads();                       // all hA(t) stores issued
        if (tid == 0) {
            asm volatile("fence.acq_rel.gpu;" ::: "memory");
            st_rel(&g_fA[bx], fbase + t + 1);  // release hA(t)
        }

        // ------- restage B half with hB(t-1) (poll released 1 step ago) ----
        if (t > 0) {
            if (tid < 16) {
                const int* fl = &g_fB[grp * 16 + tid];
                while (ld_acq(fl) - fbase < t) __nanosleep(20);
            }
            __syncthreads();                   // acquire visible to all
            int b = 4 + (tid >> 6);
            int rr = tid & 63;
            const float4* src =
                (const float4*)(out + (size_t)(t - 1) * BH + (size_t)(gb + b) * 512);
#pragma unroll
            for (int j = 0; j < 2; j++) {
                int k4 = j * 64 + rr;
                h_s4[b][k4 & 7][k4 >> 3] = __ldcg(src + k4);
            }
            __syncthreads();                   // restaged hB(t-1) visible
        }

        // ---------------- half B: batches 4..7 (reads h_s4[4..7]) ----------
        {
            float mz0 = 0.f, mz1 = 0.f, mn0 = 0.f, mn1 = 0.f;
#pragma unroll
            for (int b = 4; b < 8; b++) {
                ull az0 = 0, az1 = 0, an0 = 0, an1 = 0;
#pragma unroll
                for (int q = 0; q < 8; q++) {
                    ulonglong2 h2 = *(const ulonglong2*)&h_s4[b][q][kp];
                    az0 = fma2(wz0[q].x, h2.x, az0);
                    az0 = fma2(wz0[q].y, h2.y, az0);
                    az1 = fma2(wz1[q].x, h2.x, az1);
                    az1 = fma2(wz1[q].y, h2.y, az1);
                    an0 = fma2(wn0[q].x, h2.x, an0);
                    an0 = fma2(wn0[q].y, h2.y, an0);
                    an1 = fma2(wn1[q].x, h2.x, an1);
                    an1 = fma2(wn1[q].y, h2.y, an1);
                }
                float rz0 = sum2(az0), rz1 = sum2(az1);
                float rn0 = sum2(an0), rn1 = sum2(an1);
#pragma unroll
                for (int off = 1; off < 16; off <<= 1) {
                    rz0 += __shfl_xor_sync(0xffffffffu, rz0, off);
                    rz1 += __shfl_xor_sync(0xffffffffu, rz1, off);
                    rn0 += __shfl_xor_sync(0xffffffffu, rn0, off);
                    rn1 += __shfl_xor_sync(0xffffffffu, rn1, off);
                }
                if (kp == b) { mz0 = rz0; mz1 = rz1; mn0 = rn0; mn1 = rn1; }
            }
            if (kp >= 4 && kp < 8) {  // epilogue for batches 4..7 (eb = kp)
                float4 ho4 = h_s4[eb][k4h & 7][k4h >> 3];
                float ho0 = (hdp & 2) ? ho4.z : ho4.x;
                float ho1 = (hdp & 2) ? ho4.w : ho4.y;
                float z0 = fsig(pgz.x + mz0);
                float z1 = fsig(pgz.y + mz1);
                float n0v = ftanh(pgn.x + mn0);
                float n1v = ftanh(pgn.y + mn1);
                float2 hv;
                hv.x = ho0 + z0 * (n0v - ho0);
                hv.y = ho1 + z1 * (n1v - ho1);
                float* dst = out + (size_t)t * BH + (size_t)(gb + eb) * 512 + hdp;
                *(float2*)dst = hv;
                if (t == S_LEN - 1)
                    *(float2*)(out + (size_t)S_LEN * BH + (size_t)(gb + eb) * 512 + hdp) = hv;
            }
        }
        __syncthreads();                       // all hB(t) stores issued
        if (tid == 0) {
            asm volatile("fence.acq_rel.gpu;" ::: "memory");
            st_rel(&g_fB[bx], fbase + t + 1);  // release hB(t)
        }

        // ------- restage A half with hA(t) (poll released 1 half ago) ------
        if (t < S_LEN - 1) {
            if (tid < 16) {
                const int* fl = &g_fA[grp * 16 + tid];
                while (ld_acq(fl) - fbase < t + 1) __nanosleep(20);
            }
            __syncthreads();
            int b = tid >> 6;
            int rr = tid & 63;
            const float4* src =
                (const float4*)(out + (size_t)t * BH + (size_t)(gb + b) * 512);
#pragma unroll
            for (int j = 0; j < 2; j++) {
                int k4 = j * 64 + rr;
                h_s4[b][k4 & 7][k4 >> 3] = __ldcg(src + k4);
            }
            __syncthreads();
        }
    }
}

extern "C" void kernel_launch(void* const* d_in, const int* in_sizes, int n_in,
                              void* d_out, int out_size) {
    const float* x   = (const float*)d_in[0];  // (S, B, I)
    const float* h0  = (const float*)d_in[1];  // (1, B, H)
    const float* wih = (const float*)d_in[2];  // (3H, I)
    const float* whh = (const float*)d_in[3];  // (3H, H)
    const float* bih = (const float*)d_in[4];  // (3H,)
    const float* bhh = (const float*)d_in[5];  // (3H,)
    float* out = (float*)d_out;                // (1,S,B,H) then (1,B,H)

    dim3 ggrid(8, 1024);
    gx_gemm<<<ggrid, 256>>>(x, wih, bih, bhh);
    rec_kernel<<<128, 256>>>(h0, whh, out);
}

// round 11
// speedup vs baseline: 1.6417x; 1.2321x over previous
#include <cuda_runtime.h>
#include <cuda_bf16.h>
#include <cstddef>
#include <cstdint>

#define S_LEN 2048
#define B_DIM 64
#define I_DIM 512
#define H_DIM 512
#define BH (B_DIM * H_DIM)          // 32768
#define GX_COLS 1024                // z gates [0,512), n gates [512,1024)

// Scratch: gx[t][b][g], g in 0..1023 maps to weight rows 512+g. 512 MB.
__device__ float g_gx[(size_t)S_LEN * B_DIM * GX_COLS];
// Sense-reversing group barrier state (8 groups). Returns to {0,0} after the
// even number (2048) of flips each launch -> replay-safe.
__device__ int g_cnt[8];
__device__ int g_sense[8];

typedef unsigned long long ull;

__device__ __forceinline__ ull fma2(ull a, ull b, ull c) {
    ull d;
    asm("fma.rn.f32x2 %0, %1, %2, %3;" : "=l"(d) : "l"(a), "l"(b), "l"(c));
    return d;
}
__device__ __forceinline__ float sum2(ull u) {
    float lo, hi;
    asm("mov.b64 {%0,%1}, %2;" : "=f"(lo), "=f"(hi) : "l"(u));
    return lo + hi;
}
__device__ __forceinline__ void st_rel(int* p, int v) {
    asm volatile("st.release.gpu.global.b32 [%0], %1;" :: "l"(p), "r"(v) : "memory");
}
__device__ __forceinline__ int ld_acq(const int* p) {
    int v;
    asm volatile("ld.acquire.gpu.global.b32 %0, [%1];" : "=r"(v) : "l"(p) : "memory");
    return v;
}
// Fast gates: MUFU-based, ~1e-7 abs error, saturate correctly at +-inf.
__device__ __forceinline__ float fsig(float x) {
    return __fdividef(1.0f, 1.0f + __expf(-x));
}
__device__ __forceinline__ float ftanh(float x) {
    return 1.0f - __fdividef(2.0f, __expf(2.0f * x) + 1.0f);
}

// ---------------------------------------------------------------------------
// Kernel 1: gx = x @ Wih[512:1536]^T + (bias_ih + bias_hh)[512:1536]
// Tensor-core version: bf16 hi/lo error-compensated split (3 mma products,
// fp32 accumulate): D = Xh*Wh + Xh*Wl + Xl*Wh, error ~2^-18 per product.
// M=131072, N=1024, K=512. BM=128, BN=128, BK=32. 256 threads, 8 warps
// (4 m x 2 n), warp tile 32x64 via mma.m16n8k16.
// SMEM rows padded to 40 bf16 (20 b32): banks (20r+c) mod 32 all-distinct
// for r in 0..7 x c in 0..3 -> conflict-free fragment LDS.
// ---------------------------------------------------------------------------
__device__ __forceinline__ void split_bf16(float v, __nv_bfloat16& h, __nv_bfloat16& l) {
    h = __float2bfloat16_rn(v);
    l = __float2bfloat16_rn(v - __bfloat162float(h));
}

__global__ void __launch_bounds__(256, 1)
gx_gemm(const float* __restrict__ x, const float* __restrict__ wih,
        const float* __restrict__ bih, const float* __restrict__ bhh) {
    __shared__ __nv_bfloat162 AsH[128 * 20];
    __shared__ __nv_bfloat162 AsL[128 * 20];
    __shared__ __nv_bfloat162 BsH[128 * 20];
    __shared__ __nv_bfloat162 BsL[128 * 20];

    const int tid = threadIdx.x;
    const int lane = tid & 31;
    const int wid = tid >> 5;
    const int wm = (wid & 3) * 32;       // warp m offset in tile
    const int wn = (wid >> 2) * 64;      // warp n offset in tile
    const int n0 = blockIdx.x * 128;
    const size_t m0 = (size_t)blockIdx.y * 128;

    // Staging assignment: 2 threads per row, 16 k each.
    const int row = tid >> 1;            // 0..127
    const int koff = (tid & 1) * 16;     // 0 or 16
    const int ebase = row * 20 + (koff >> 1);
    const float* asrc = x + (m0 + row) * 512 + koff;
    const float* bsrc = wih + (size_t)(512 + n0 + row) * 512 + koff;

    float acc[2][8][4];
#pragma unroll
    for (int mt = 0; mt < 2; mt++)
#pragma unroll
        for (int nt = 0; nt < 8; nt++)
#pragma unroll
            for (int i = 0; i < 4; i++) acc[mt][nt][i] = 0.f;

    float4 af[4], bf[4];
#pragma unroll
    for (int j = 0; j < 4; j++) {
        af[j] = *(const float4*)(asrc + j * 4);
        bf[j] = *(const float4*)(bsrc + j * 4);
    }

    const uint32_t* AH = (const uint32_t*)AsH;
    const uint32_t* AL = (const uint32_t*)AsL;
    const uint32_t* BBH = (const uint32_t*)BsH;
    const uint32_t* BBL = (const uint32_t*)BsL;

    for (int s = 0; s < 16; s++) {
        // Store prefetched chunk (convert fp32 -> bf16 hi/lo).
#pragma unroll
        for (int j = 0; j < 4; j++) {
            __nv_bfloat16 hx, lx, hy, ly, hz, lz, hw, lw;
            split_bf16(af[j].x, hx, lx); split_bf16(af[j].y, hy, ly);
            split_bf16(af[j].z, hz, lz); split_bf16(af[j].w, hw, lw);
            AsH[ebase + j * 2]     = __halves2bfloat162(hx, hy);
            AsH[ebase + j * 2 + 1] = __halves2bfloat162(hz, hw);
            AsL[ebase + j * 2]     = __halves2bfloat162(lx, ly);
            AsL[ebase + j * 2 + 1] = __halves2bfloat162(lz, lw);
            split_bf16(bf[j].x, hx, lx); split_bf16(bf[j].y, hy, ly);
            split_bf16(bf[j].z, hz, lz); split_bf16(bf[j].w, hw, lw);
            BsH[ebase + j * 2]     = __halves2bfloat162(hx, hy);
            BsH[ebase + j * 2 + 1] = __halves2bfloat162(hz, hw);
            BsL[ebase + j * 2]     = __halves2bfloat162(lx, ly);
            BsL[ebase + j * 2 + 1] = __halves2bfloat162(lz, lw);
        }
        __syncthreads();

        if (s < 15) {
            int kn = (s + 1) * 32;
#pragma unroll
            for (int j = 0; j < 4; j++) {
                af[j] = *(const float4*)(asrc + kn + j * 4);
                bf[j] = *(const float4*)(bsrc + kn + j * 4);
            }
        }

#pragma unroll
        for (int ks = 0; ks < 2; ks++) {
            const int ke = ks * 8 + (lane & 3);
            // A fragments for both m-tiles, hi and lo.
            uint32_t ah[2][4], al[2][4];
#pragma unroll
            for (int mt = 0; mt < 2; mt++) {
                int r = wm + mt * 16 + (lane >> 2);
                ah[mt][0] = AH[r * 20 + ke];
                ah[mt][1] = AH[(r + 8) * 20 + ke];
                ah[mt][2] = AH[r * 20 + ke + 4];
                ah[mt][3] = AH[(r + 8) * 20 + ke + 4];
                al[mt][0] = AL[r * 20 + ke];
                al[mt][1] = AL[(r + 8) * 20 + ke];
                al[mt][2] = AL[r * 20 + ke + 4];
                al[mt][3] = AL[(r + 8) * 20 + ke + 4];
            }
#pragma unroll
            for (int nt = 0; nt < 8; nt++) {
                int nr = wn + nt * 8 + (lane >> 2);
                uint32_t bh0 = BBH[nr * 20 + ke];
                uint32_t bh1 = BBH[nr * 20 + ke + 4];
                uint32_t bl0 = BBL[nr * 20 + ke];
                uint32_t bl1 = BBL[nr * 20 + ke + 4];
#pragma unroll
                for (int mt = 0; mt < 2; mt++) {
                    float* c = acc[mt][nt];
                    asm("mma.sync.aligned.m16n8k16.row.col.f32.bf16.bf16.f32 "
                        "{%0,%1,%2,%3}, {%4,%5,%6,%7}, {%8,%9}, {%0,%1,%2,%3};"
                        : "+f"(c[0]), "+f"(c[1]), "+f"(c[2]), "+f"(c[3])
                        : "r"(ah[mt][0]), "r"(ah[mt][1]), "r"(ah[mt][2]), "r"(ah[mt][3]),
                          "r"(bh0), "r"(bh1));
                    asm("mma.sync.aligned.m16n8k16.row.col.f32.bf16.bf16.f32 "
                        "{%0,%1,%2,%3}, {%4,%5,%6,%7}, {%8,%9}, {%0,%1,%2,%3};"
                        : "+f"(c[0]), "+f"(c[1]), "+f"(c[2]), "+f"(c[3])
                        : "r"(ah[mt][0]), "r"(ah[mt][1]), "r"(ah[mt][2]), "r"(ah[mt][3]),
                          "r"(bl0), "r"(bl1));
                    asm("mma.sync.aligned.m16n8k16.row.col.f32.bf16.bf16.f32 "
                        "{%0,%1,%2,%3}, {%4,%5,%6,%7}, {%8,%9}, {%0,%1,%2,%3};"
                        : "+f"(c[0]), "+f"(c[1]), "+f"(c[2]), "+f"(c[3])
                        : "r"(al[mt][0]), "r"(al[mt][1]), "r"(al[mt][2]), "r"(al[mt][3]),
                          "r"(bh0), "r"(bh1));
                }
            }
        }
        __syncthreads();
    }

    // Epilogue: C frag (mt,nt): rows m0+wm+mt*16+(lane>>2) (+8), cols
    // n0+wn+nt*8+(lane&3)*2 (+1). Add fused bias, store float2.
#pragma unroll
    for (int nt = 0; nt < 8; nt++) {
        int n = n0 + wn + nt * 8 + (lane & 3) * 2;
        float bz0 = bih[512 + n] + bhh[512 + n];
        float bz1 = bih[513 + n] + bhh[513 + n];
#pragma unroll
        for (int mt = 0; mt < 2; mt++) {
            size_t m = m0 + wm + mt * 16 + (lane >> 2);
            float* p0 = g_gx + m * GX_COLS + n;
            float* p1 = g_gx + (m + 8) * GX_COLS + n;
            float2 v0 = make_float2(acc[mt][nt][0] + bz0, acc[mt][nt][1] + bz1);
            float2 v1 = make_float2(acc[mt][nt][2] + bz0, acc[mt][nt][3] + bz1);
            *(float2*)p0 = v0;
            *(float2*)p1 = v1;
        }
    }
}

// ---------------------------------------------------------------------------
// Kernel 2: recurrence — EXACT R7 source (best measured, 11.38 ms total).
// 128 CTAs = 8 groups x 16 CTAs; group g: batches 8g..8g+7; CTA c: h-dims
// [32c, 32c+32). 256 threads; thread (wid,lane): hdg = wid*2 + (lane>>4),
// kp = lane&15; owns rows {z0,z1,n0,n1} of hd pair {hd0+2hdg, +1} over k in
// [32kp, 32kp+32): 128 weight floats in registers, step-invariant.
// ---------------------------------------------------------------------------
__global__ void __launch_bounds__(256, 1)
rec_kernel(const float* __restrict__ h0, const float* __restrict__ whh,
           float* __restrict__ out) {
    __shared__ float4 h_s4[8][8][17];   // [b][q][kp] swizzled, k=(kp*8+q)*4+e

    const int tid = threadIdx.x;
    const int bx = blockIdx.x;
    const int grp = bx >> 4;
    const int gb = grp * 8;
    const int hd0 = (bx & 15) * 32;
    const int lane = tid & 31;
    const int wid = tid >> 5;
    const int kp = lane & 15;
    const int h1 = lane >> 4;
    const int hdg = wid * 2 + h1;
    const int hdp = hd0 + hdg * 2;      // this thread's hd pair base
    const bool ep = (kp < 8);           // epilogue lane: handles batch eb
    const int eb = kp;
    const int k4h = hdp >> 2;           // h_old float4 slot for this hd pair

    // Step-invariant weights in registers (128 floats).
    ulonglong2 wz0[8], wz1[8], wn0[8], wn1[8];
    {
        const ulonglong2* pz0 = (const ulonglong2*)(whh + (size_t)(512 + hdp) * 512 + kp * 32);
        const ulonglong2* pz1 = (const ulonglong2*)(whh + (size_t)(513 + hdp) * 512 + kp * 32);
        const ulonglong2* pn0 = (const ulonglong2*)(whh + (size_t)(1024 + hdp) * 512 + kp * 32);
        const ulonglong2* pn1 = (const ulonglong2*)(whh + (size_t)(1025 + hdp) * 512 + kp * 32);
#pragma unroll
        for (int q = 0; q < 8; q++) {
            wz0[q] = pz0[q];
            wz1[q] = pz1[q];
            wn0[q] = pn0[q];
            wn1[q] = pn1[q];
        }
    }

    // Stage h(-1) = h_0 into swizzled SMEM.
    {
        int b = tid >> 5, rr = tid & 31;
        const float4* src = (const float4*)(h0 + (size_t)(gb + b) * 512);
#pragma unroll
        for (int j = 0; j < 4; j++) {
            int k4 = j * 32 + rr;
            h_s4[b][k4 & 7][k4 >> 3] = __ldcg(src + k4);
        }
    }
    __syncthreads();

    int sense = 0;

    for (int t = 0; t < S_LEN; t++) {
        // Distributed prefetch: each epilogue lane loads only its own cells.
        float2 pgz = make_float2(0.f, 0.f), pgn = make_float2(0.f, 0.f);
        if (ep) {
            const float* gxt = g_gx + (size_t)t * B_DIM * GX_COLS + (size_t)(gb + eb) * GX_COLS;
            pgz = __ldcg((const float2*)(gxt + hdp));
            pgn = __ldcg((const float2*)(gxt + 512 + hdp));
        }

        float mz0 = 0.f, mz1 = 0.f, mn0 = 0.f, mn1 = 0.f;
#pragma unroll
        for (int b = 0; b < 8; b++) {
            ull az0 = 0, az1 = 0, an0 = 0, an1 = 0;
#pragma unroll
            for (int q = 0; q < 8; q++) {
                ulonglong2 h2 = *(const ulonglong2*)&h_s4[b][q][kp];
                az0 = fma2(wz0[q].x, h2.x, az0);
                az0 = fma2(wz0[q].y, h2.y, az0);
                az1 = fma2(wz1[q].x, h2.x, az1);
                az1 = fma2(wz1[q].y, h2.y, az1);
                an0 = fma2(wn0[q].x, h2.x, an0);
                an0 = fma2(wn0[q].y, h2.y, an0);
                an1 = fma2(wn1[q].x, h2.x, an1);
                an1 = fma2(wn1[q].y, h2.y, an1);
            }
            float rz0 = sum2(az0), rz1 = sum2(az1);
            float rn0 = sum2(an0), rn1 = sum2(an1);
#pragma unroll
            for (int off = 1; off < 16; off <<= 1) {
                rz0 += __shfl_xor_sync(0xffffffffu, rz0, off);
                rz1 += __shfl_xor_sync(0xffffffffu, rz1, off);
                rn0 += __shfl_xor_sync(0xffffffffu, rn0, off);
                rn1 += __shfl_xor_sync(0xffffffffu, rn1, off);
            }
            // All 16 lanes of this half now hold identical sums; lane kp==b
            // keeps batch b's values for the distributed epilogue.
            if (kp == b) { mz0 = rz0; mz1 = rz1; mn0 = rn0; mn1 = rn1; }
        }

        // Distributed epilogue: lanes kp<8 each update (batch eb, hd pair).
        if (ep) {
            float4 ho4 = h_s4[eb][k4h & 7][k4h >> 3];
            float ho0 = (hdp & 2) ? ho4.z : ho4.x;
            float ho1 = (hdp & 2) ? ho4.w : ho4.y;
            float z0 = fsig(pgz.x + mz0);
            float z1 = fsig(pgz.y + mz1);
            float n0v = ftanh(pgn.x + mn0);
            float n1v = ftanh(pgn.y + mn1);
            float2 hv;
            hv.x = ho0 + z0 * (n0v - ho0);
            hv.y = ho1 + z1 * (n1v - ho1);
            float* dst = out + (size_t)t * BH + (size_t)(gb + eb) * 512 + hdp;
            *(float2*)dst = hv;
            if (t == S_LEN - 1) {
                float* dn = out + (size_t)S_LEN * BH + (size_t)(gb + eb) * 512 + hdp;
                *(float2*)dn = hv;
            }
        }

        // Group barrier. bar.sync orders all CTA threads' h stores before
        // tid0; tid0's gpu-scope fence + release publish them; pollers use
        // acquire so the post-barrier restage sees all h[t].
        __syncthreads();
        sense ^= 1;
        if (tid == 0) {
            asm volatile("fence.acq_rel.gpu;" ::: "memory");
            if (atomicAdd(&g_cnt[grp], 1) == 15) {
                g_cnt[grp] = 0;
                st_rel(&g_sense[grp], sense);
            } else {
                while (ld_acq(&g_sense[grp]) != sense) __nanosleep(32);
            }
        }
        __syncthreads();

        // Restage h[t] from out (L2) into swizzled SMEM.
        {
            int b = tid >> 5, rr = tid & 31;
            const float4* src = (const float4*)(out + (size_t)t * BH + (size_t)(gb + b) * 512);
#pragma unroll
            for (int j = 0; j < 4; j++) {
                int k4 = j * 32 + rr;
                h_s4[b][k4 & 7][k4 >> 3] = __ldcg(src + k4);
            }
        }
        __syncthreads();
    }
}

extern "C" void kernel_launch(void* const* d_in, const int* in_sizes, int n_in,
                              void* d_out, int out_size) {
    const float* x   = (const float*)d_in[0];  // (S, B, I)
    const float* h0  = (const float*)d_in[1];  // (1, B, H)
    const float* wih = (const float*)d_in[2];  // (3H, I)
    const float* whh = (const float*)d_in[3];  // (3H, H)
    const float* bih = (const float*)d_in[4];  // (3H,)
    const float* bhh = (const float*)d_in[5];  // (3H,)
    float* out = (float*)d_out;                // (1,S,B,H) then (1,B,H)

    dim3 ggrid(8, 1024);                       // N-tiles x M-tiles
    gx_gemm<<<ggrid, 256>>>(x, wih, bih, bhh);
    rec_kernel<<<128, 256>>>(h0, whh, out);
}

// round 12
// speedup vs baseline: 1.6884x; 1.0285x over previous
#include <cuda_runtime.h>
#include <cuda_bf16.h>
#include <cstddef>
#include <cstdint>

#define S_LEN 2048
#define B_DIM 64
#define I_DIM 512
#define H_DIM 512
#define BH (B_DIM * H_DIM)          // 32768
#define GX_COLS 1024                // z gates [0,512), n gates [512,1024)
#define M_TOT ((size_t)S_LEN * B_DIM)   // 131072

// Scratch: gx[t][b][g], g in 0..1023 maps to weight rows 512+g. 512 MB.
__device__ float g_gx[(size_t)S_LEN * B_DIM * GX_COLS];
// Pre-split bf16 operands (hi/lo error-compensated split).
__device__ __nv_bfloat16 g_xh[M_TOT * I_DIM];
__device__ __nv_bfloat16 g_xl[M_TOT * I_DIM];
__device__ __nv_bfloat16 g_wh[1024 * I_DIM];
__device__ __nv_bfloat16 g_wl[1024 * I_DIM];
// Sense-reversing group barrier state (8 groups). Returns to {0,0} after the
// even number (2048) of flips each launch -> replay-safe.
__device__ int g_cnt[8];
__device__ int g_sense[8];

typedef unsigned long long ull;

__device__ __forceinline__ ull fma2(ull a, ull b, ull c) {
    ull d;
    asm("fma.rn.f32x2 %0, %1, %2, %3;" : "=l"(d) : "l"(a), "l"(b), "l"(c));
    return d;
}
__device__ __forceinline__ float sum2(ull u) {
    float lo, hi;
    asm("mov.b64 {%0,%1}, %2;" : "=f"(lo), "=f"(hi) : "l"(u));
    return lo + hi;
}
__device__ __forceinline__ void st_rel(int* p, int v) {
    asm volatile("st.release.gpu.global.b32 [%0], %1;" :: "l"(p), "r"(v) : "memory");
}
__device__ __forceinline__ int ld_acq(const int* p) {
    int v;
    asm volatile("ld.acquire.gpu.global.b32 %0, [%1];" : "=r"(v) : "l"(p) : "memory");
    return v;
}
__device__ __forceinline__ float fsig(float x) {
    return __fdividef(1.0f, 1.0f + __expf(-x));
}
__device__ __forceinline__ float ftanh(float x) {
    return 1.0f - __fdividef(2.0f, __expf(2.0f * x) + 1.0f);
}
__device__ __forceinline__ void split_bf16(float v, __nv_bfloat16& h, __nv_bfloat16& l) {
    h = __float2bfloat16_rn(v);
    l = __float2bfloat16_rn(v - __bfloat162float(h));
}
__device__ __forceinline__ void cp16(uint32_t saddr, const void* gaddr) {
    asm volatile("cp.async.cg.shared.global [%0], [%1], 16;"
                 :: "r"(saddr), "l"(gaddr));
}

// ---------------------------------------------------------------------------
// Pre-pass: fp32 -> bf16 hi/lo split. Each thread converts 8 elements.
// ---------------------------------------------------------------------------
__global__ void __launch_bounds__(256, 1)
conv_split(const float* __restrict__ src, __nv_bfloat16* __restrict__ dh,
           __nv_bfloat16* __restrict__ dl) {
    size_t i = ((size_t)blockIdx.x * 256 + threadIdx.x) * 8;
    float4 a = *(const float4*)(src + i);
    float4 b = *(const float4*)(src + i + 4);
    __nv_bfloat16 h[8], l[8];
    split_bf16(a.x, h[0], l[0]); split_bf16(a.y, h[1], l[1]);
    split_bf16(a.z, h[2], l[2]); split_bf16(a.w, h[3], l[3]);
    split_bf16(b.x, h[4], l[4]); split_bf16(b.y, h[5], l[5]);
    split_bf16(b.z, h[6], l[6]); split_bf16(b.w, h[7], l[7]);
    *(uint4*)(dh + i) = *(const uint4*)h;
    *(uint4*)(dl + i) = *(const uint4*)l;
}

// ---------------------------------------------------------------------------
// Kernel 1: gx = x @ Wih[512:1536]^T + (bias_ih + bias_hh)[512:1536]
// bf16 hi/lo compensated split (3 mma products, fp32 accum), operands
// PRE-SPLIT in global. BM=BN=128, BK=32, 256 threads, 8 warps (4m x 2n),
// warp tile 32x64 via mma.m16n8k16. Double-buffered cp.async staging.
// SMEM rows stride 20 b32 (40 bf16): banks (20r+c)%32 all-distinct for the
// fragment pattern -> conflict-free LDS; 16B-aligned for cp.async.
// ---------------------------------------------------------------------------
__global__ void __launch_bounds__(256, 1)
gx_gemm(const float* __restrict__ bih, const float* __restrict__ bhh) {
    __shared__ uint32_t SAH[2][128 * 20];
    __shared__ uint32_t SAL[2][128 * 20];
    __shared__ uint32_t SBH[2][128 * 20];
    __shared__ uint32_t SBL[2][128 * 20];

    const int tid = threadIdx.x;
    const int lane = tid & 31;
    const int wid = tid >> 5;
    const int wm = (wid & 3) * 32;
    const int wn = (wid >> 2) * 64;
    const int n0 = blockIdx.x * 128;
    const size_t m0 = (size_t)blockIdx.y * 128;

    // Staging: row r = tid>>1, k-half kh = tid&1 (16 bf16 = 32B = 2 chunks).
    const int row = tid >> 1;
    const int kh = tid & 1;
    const uint32_t soff = (uint32_t)(row * 20 + kh * 8) * 4;  // byte offset
    const __nv_bfloat16* axh = g_xh + (m0 + row) * I_DIM + kh * 16;
    const __nv_bfloat16* axl = g_xl + (m0 + row) * I_DIM + kh * 16;
    const __nv_bfloat16* bwh = g_wh + (size_t)(n0 + row) * I_DIM + kh * 16;
    const __nv_bfloat16* bwl = g_wl + (size_t)(n0 + row) * I_DIM + kh * 16;

    const uint32_t sAH0 = (uint32_t)__cvta_generic_to_shared(&SAH[0][0]);
    const uint32_t sAL0 = (uint32_t)__cvta_generic_to_shared(&SAL[0][0]);
    const uint32_t sBH0 = (uint32_t)__cvta_generic_to_shared(&SBH[0][0]);
    const uint32_t sBL0 = (uint32_t)__cvta_generic_to_shared(&SBL[0][0]);
    const uint32_t bufstride = 128 * 20 * 4;

    float acc[2][8][4];
#pragma unroll
    for (int mt = 0; mt < 2; mt++)
#pragma unroll
        for (int nt = 0; nt < 8; nt++)
#pragma unroll
            for (int i = 0; i < 4; i++) acc[mt][nt][i] = 0.f;

    auto issue_stage = [&](int s, int buf) {
        int ko = s * 32;
        uint32_t bo = buf * bufstride + soff;
        cp16(sAH0 + bo, axh + ko);
        cp16(sAH0 + bo + 16, axh + ko + 8);
        cp16(sAL0 + bo, axl + ko);
        cp16(sAL0 + bo + 16, axl + ko + 8);
        cp16(sBH0 + bo, bwh + ko);
        cp16(sBH0 + bo + 16, bwh + ko + 8);
        cp16(sBL0 + bo, bwl + ko);
        cp16(sBL0 + bo + 16, bwl + ko + 8);
        asm volatile("cp.async.commit_group;" ::: "memory");
    };

    issue_stage(0, 0);

    for (int s = 0; s < 16; s++) {
        const int buf = s & 1;
        if (s < 15) {
            issue_stage(s + 1, buf ^ 1);
            asm volatile("cp.async.wait_group 1;" ::: "memory");
        } else {
            asm volatile("cp.async.wait_group 0;" ::: "memory");
        }
        __syncthreads();

        const uint32_t* AH = &SAH[buf][0];
        const uint32_t* AL = &SAL[buf][0];
        const uint32_t* BBH = &SBH[buf][0];
        const uint32_t* BBL = &SBL[buf][0];

#pragma unroll
        for (int ks = 0; ks < 2; ks++) {
            const int ke = ks * 8 + (lane & 3);
            uint32_t ah[2][4], al[2][4];
#pragma unroll
            for (int mt = 0; mt < 2; mt++) {
                int r = wm + mt * 16 + (lane >> 2);
                ah[mt][0] = AH[r * 20 + ke];
                ah[mt][1] = AH[(r + 8) * 20 + ke];
                ah[mt][2] = AH[r * 20 + ke + 4];
                ah[mt][3] = AH[(r + 8) * 20 + ke + 4];
                al[mt][0] = AL[r * 20 + ke];
                al[mt][1] = AL[(r + 8) * 20 + ke];
                al[mt][2] = AL[r * 20 + ke + 4];
                al[mt][3] = AL[(r + 8) * 20 + ke + 4];
            }
#pragma unroll
            for (int nt = 0; nt < 8; nt++) {
                int nr = wn + nt * 8 + (lane >> 2);
                uint32_t bh0 = BBH[nr * 20 + ke];
                uint32_t bh1 = BBH[nr * 20 + ke + 4];
                uint32_t bl0 = BBL[nr * 20 + ke];
                uint32_t bl1 = BBL[nr * 20 + ke + 4];
#pragma unroll
                for (int mt = 0; mt < 2; mt++) {
                    float* c = acc[mt][nt];
                    asm("mma.sync.aligned.m16n8k16.row.col.f32.bf16.bf16.f32 "
                        "{%0,%1,%2,%3}, {%4,%5,%6,%7}, {%8,%9}, {%0,%1,%2,%3};"
                        : "+f"(c[0]), "+f"(c[1]), "+f"(c[2]), "+f"(c[3])
                        : "r"(ah[mt][0]), "r"(ah[mt][1]), "r"(ah[mt][2]), "r"(ah[mt][3]),
                          "r"(bh0), "r"(bh1));
                    asm("mma.sync.aligned.m16n8k16.row.col.f32.bf16.bf16.f32 "
                        "{%0,%1,%2,%3}, {%4,%5,%6,%7}, {%8,%9}, {%0,%1,%2,%3};"
                        : "+f"(c[0]), "+f"(c[1]), "+f"(c[2]), "+f"(c[3])
                        : "r"(ah[mt][0]), "r"(ah[mt][1]), "r"(ah[mt][2]), "r"(ah[mt][3]),
                          "r"(bl0), "r"(bl1));
                    asm("mma.sync.aligned.m16n8k16.row.col.f32.bf16.bf16.f32 "
                        "{%0,%1,%2,%3}, {%4,%5,%6,%7}, {%8,%9}, {%0,%1,%2,%3};"
                        : "+f"(c[0]), "+f"(c[1]), "+f"(c[2]), "+f"(c[3])
                        : "r"(al[mt][0]), "r"(al[mt][1]), "r"(al[mt][2]), "r"(al[mt][3]),
                          "r"(bh0), "r"(bh1));
                }
            }
        }
        __syncthreads();
    }

    // Epilogue: rows m0+wm+mt*16+(lane>>2) (+8), cols n0+wn+nt*8+(lane&3)*2.
#pragma unroll
    for (int nt = 0; nt < 8; nt++) {
        int n = n0 + wn + nt * 8 + (lane & 3) * 2;
        float bz0 = bih[512 + n] + bhh[512 + n];
        float bz1 = bih[513 + n] + bhh[513 + n];
#pragma unroll
        for (int mt = 0; mt < 2; mt++) {
            size_t m = m0 + wm + mt * 16 + (lane >> 2);
            float* p0 = g_gx + m * GX_COLS + n;
            float* p1 = g_gx + (m + 8) * GX_COLS + n;
            *(float2*)p0 = make_float2(acc[mt][nt][0] + bz0, acc[mt][nt][1] + bz1);
            *(float2*)p1 = make_float2(acc[mt][nt][2] + bz0, acc[mt][nt][3] + bz1);
        }
    }
}

// ---------------------------------------------------------------------------
// Kernel 2: recurrence — EXACT R7 source (frozen; best measured).
// ---------------------------------------------------------------------------
__global__ void __launch_bounds__(256, 1)
rec_kernel(const float* __restrict__ h0, const float* __restrict__ whh,
           float* __restrict__ out) {
    __shared__ float4 h_s4[8][8][17];   // [b][q][kp] swizzled, k=(kp*8+q)*4+e

    const int tid = threadIdx.x;
    const int bx = blockIdx.x;
    const int grp = bx >> 4;
    const int gb = grp * 8;
    const int hd0 = (bx & 15) * 32;
    const int lane = tid & 31;
    const int wid = tid >> 5;
    const int kp = lane & 15;
    const int h1 = lane >> 4;
    const int hdg = wid * 2 + h1;
    const int hdp = hd0 + hdg * 2;
    const bool ep = (kp < 8);
    const int eb = kp;
    const int k4h = hdp >> 2;

    ulonglong2 wz0[8], wz1[8], wn0[8], wn1[8];
    {
        const ulonglong2* pz0 = (const ulonglong2*)(whh + (size_t)(512 + hdp) * 512 + kp * 32);
        const ulonglong2* pz1 = (const ulonglong2*)(whh + (size_t)(513 + hdp) * 512 + kp * 32);
        const ulonglong2* pn0 = (const ulonglong2*)(whh + (size_t)(1024 + hdp) * 512 + kp * 32);
        const ulonglong2* pn1 = (const ulonglong2*)(whh + (size_t)(1025 + hdp) * 512 + kp * 32);
#pragma unroll
        for (int q = 0; q < 8; q++) {
            wz0[q] = pz0[q];
            wz1[q] = pz1[q];
            wn0[q] = pn0[q];
            wn1[q] = pn1[q];
        }
    }

    {
        int b = tid >> 5, rr = tid & 31;
        const float4* src = (const float4*)(h0 + (size_t)(gb + b) * 512);
#pragma unroll
        for (int j = 0; j < 4; j++) {
            int k4 = j * 32 + rr;
            h_s4[b][k4 & 7][k4 >> 3] = __ldcg(src + k4);
        }
    }
    __syncthreads();

    int sense = 0;

    for (int t = 0; t < S_LEN; t++) {
        float2 pgz = make_float2(0.f, 0.f), pgn = make_float2(0.f, 0.f);
        if (ep) {
            const float* gxt = g_gx + (size_t)t * B_DIM * GX_COLS + (size_t)(gb + eb) * GX_COLS;
            pgz = __ldcg((const float2*)(gxt + hdp));
            pgn = __ldcg((const float2*)(gxt + 512 + hdp));
        }

        float mz0 = 0.f, mz1 = 0.f, mn0 = 0.f, mn1 = 0.f;
#pragma unroll
        for (int b = 0; b < 8; b++) {
            ull az0 = 0, az1 = 0, an0 = 0, an1 = 0;
#pragma unroll
            for (int q = 0; q < 8; q++) {
                ulonglong2 h2 = *(const ulonglong2*)&h_s4[b][q][kp];
                az0 = fma2(wz0[q].x, h2.x, az0);
                az0 = fma2(wz0[q].y, h2.y, az0);
                az1 = fma2(wz1[q].x, h2.x, az1);
                az1 = fma2(wz1[q].y, h2.y, az1);
                an0 = fma2(wn0[q].x, h2.x, an0);
                an0 = fma2(wn0[q].y, h2.y, an0);
                an1 = fma2(wn1[q].x, h2.x, an1);
                an1 = fma2(wn1[q].y, h2.y, an1);
            }
            float rz0 = sum2(az0), rz1 = sum2(az1);
            float rn0 = sum2(an0), rn1 = sum2(an1);
#pragma unroll
            for (int off = 1; off < 16; off <<= 1) {
                rz0 += __shfl_xor_sync(0xffffffffu, rz0, off);
                rz1 += __shfl_xor_sync(0xffffffffu, rz1, off);
                rn0 += __shfl_xor_sync(0xffffffffu, rn0, off);
                rn1 += __shfl_xor_sync(0xffffffffu, rn1, off);
            }
            if (kp == b) { mz0 = rz0; mz1 = rz1; mn0 = rn0; mn1 = rn1; }
        }

        if (ep) {
            float4 ho4 = h_s4[eb][k4h & 7][k4h >> 3];
            float ho0 = (hdp & 2) ? ho4.z : ho4.x;
            float ho1 = (hdp & 2) ? ho4.w : ho4.y;
            float z0 = fsig(pgz.x + mz0);
            float z1 = fsig(pgz.y + mz1);
            float n0v = ftanh(pgn.x + mn0);
            float n1v = ftanh(pgn.y + mn1);
            float2 hv;
            hv.x = ho0 + z0 * (n0v - ho0);
            hv.y = ho1 + z1 * (n1v - ho1);
            float* dst = out + (size_t)t * BH + (size_t)(gb + eb) * 512 + hdp;
            *(float2*)dst = hv;
            if (t == S_LEN - 1) {
                float* dn = out + (size_t)S_LEN * BH + (size_t)(gb + eb) * 512 + hdp;
                *(float2*)dn = hv;
            }
        }

        __syncthreads();
        sense ^= 1;
        if (tid == 0) {
            asm volatile("fence.acq_rel.gpu;" ::: "memory");
            if (atomicAdd(&g_cnt[grp], 1) == 15) {
                g_cnt[grp] = 0;
                st_rel(&g_sense[grp], sense);
            } else {
                while (ld_acq(&g_sense[grp]) != sense) __nanosleep(32);
            }
        }
        __syncthreads();

        {
            int b = tid >> 5, rr = tid & 31;
            const float4* src = (const float4*)(out + (size_t)t * BH + (size_t)(gb + b) * 512);
#pragma unroll
            for (int j = 0; j < 4; j++) {
                int k4 = j * 32 + rr;
                h_s4[b][k4 & 7][k4 >> 3] = __ldcg(src + k4);
            }
        }
        __syncthreads();
    }
}

extern "C" void kernel_launch(void* const* d_in, const int* in_sizes, int n_in,
                              void* d_out, int out_size) {
    const float* x   = (const float*)d_in[0];  // (S, B, I)
    const float* h0  = (const float*)d_in[1];  // (1, B, H)
    const float* wih = (const float*)d_in[2];  // (3H, I)
    const float* whh = (const float*)d_in[3];  // (3H, H)
    const float* bih = (const float*)d_in[4];  // (3H,)
    const float* bhh = (const float*)d_in[5];  // (3H,)
    float* out = (float*)d_out;                // (1,S,B,H) then (1,B,H)

    __nv_bfloat16 *xh, *xl, *wh, *wl;
    float* gxp;
    cudaGetSymbolAddress((void**)&xh, g_xh);
    cudaGetSymbolAddress((void**)&xl, g_xl);
    cudaGetSymbolAddress((void**)&wh, g_wh);
    cudaGetSymbolAddress((void**)&wl, g_wl);
    (void)gxp;

    // Pre-split x (67,108,864 elems) and Wih rows 512..1535 (524,288 elems).
    conv_split<<<32768, 256>>>(x, xh, xl);
    conv_split<<<256, 256>>>(wih + (size_t)512 * I_DIM, wh, wl);

    dim3 ggrid(8, 1024);                       // N-tiles x M-tiles
    gx_gemm<<<ggrid, 256>>>(bih, bhh);
    rec_kernel<<<128, 256>>>(h0, whh, out);
}